// round 15
// baseline (speedup 1.0000x reference)
#include <cuda_runtime.h>

typedef unsigned long long u64t;

__device__ __forceinline__ u64t fma2(u64t a, u64t b, u64t c) {
    u64t d;
    asm("fma.rn.f32x2 %0, %1, %2, %3;" : "=l"(d) : "l"(a), "l"(b), "l"(c));
    return d;
}
__device__ __forceinline__ u64t add2(u64t a, u64t b) {
    u64t d;
    asm("add.rn.f32x2 %0, %1, %2;" : "=l"(d) : "l"(a), "l"(b));
    return d;
}
__device__ __forceinline__ u64t pk2(float lo, float hi) {
    u64t d;
    asm("mov.b64 %0, {%1, %2};" : "=l"(d) : "f"(lo), "f"(hi));
    return d;
}
__device__ __forceinline__ void unpk(u64t v, float& lo, float& hi) {
    asm("mov.b64 {%0, %1}, %2;" : "=f"(lo), "=f"(hi) : "l"(v));
}
__device__ __forceinline__ float fsqrt_ap(float x) {
    float y;
    asm("sqrt.approx.f32 %0, %1;" : "=f"(y) : "f"(x));
    return y;
}
__device__ __forceinline__ u64t shx1(u64t v) {
    unsigned lo = (unsigned)v, hi = (unsigned)(v >> 32);
    lo = __shfl_xor_sync(0xffffffffu, lo, 1);
    hi = __shfl_xor_sync(0xffffffffu, hi, 1);
    return ((u64t)hi << 32) | lo;
}

// ---- weight region (u64t units), R10 packed layout (sW0 unpermuted) ----
// x-order (new k): [rot 0..8, jtr 9..11, feat 12..17, bone 18, pad 19]
//   old-k map K(m): m<12 -> m ; 12..17 -> m+1 ; 18 -> 12 ; 19 -> zero
// sW1': [24 j][10 kp][20 r]  u64 = (W1[j][r][K(2kp)], W1[j][r][K(2kp+1)])
// sW2 : [24 j][20 k][3 dp]   (k=19 row = b2; fed by hs[9]==1 on odd lane)
// sW0': [144 kp][6 d]        u64 = (W0[d][2kp], W0[d][2kp+1]) (plain order)
// sB1': [24 j][20 r]         u64 = (b1, 0)
// sB0': [6 d]                u64 = (b0, 0)
#define OW1 0
#define OW2 4800
#define OW0 6240
#define OB1 7104
#define OB0 7584
#define SM_U64 7590            // 60720 B (weights only)
#define SMEM_BYTES (SM_U64 * 8)

template<int J, int PS, int WS>
__device__ __forceinline__ void do_joint(
    const float* __restrict__ reA, const float* __restrict__ teA,
    const float* __restrict__ reB, const float* __restrict__ teB,
    float* __restrict__ oeA, float* __restrict__ oeB,
    int half, const u64t* __restrict__ sm,
    u64t (&fA)[4][3], u64t (&fB)[4][3],
    float (&jxA)[4], float (&jyA)[4], float (&jzA)[4],
    float (&jxB)[4], float (&jyB)[4], float (&jzB)[4],
    const u64t (&gA)[3], const u64t (&gB)[3])
{
    // inputs for both elements (independent of chain -> hoistable LDG)
    float a0 = reA[9*J+0], a1 = reA[9*J+1], a2 = reA[9*J+2],
          a3 = reA[9*J+3], a4 = reA[9*J+4], a5 = reA[9*J+5],
          a6 = reA[9*J+6], a7 = reA[9*J+7], a8 = reA[9*J+8];
    float ja0 = teA[3*J+0], ja1 = teA[3*J+1], ja2 = teA[3*J+2];
    float b0 = reB[9*J+0], b1 = reB[9*J+1], b2 = reB[9*J+2],
          b3 = reB[9*J+3], b4 = reB[9*J+4], b5 = reB[9*J+5],
          b6 = reB[9*J+6], b7 = reB[9*J+7], b8 = reB[9*J+8];
    float jb0 = teB[3*J+0], jb1 = teB[3*J+1], jb2 = teB[3*J+2];

    float dxA, dyA, dzA, dxB, dyB, dzB;
    if (PS < 0) {
        dxA = ja0; dyA = ja1; dzA = ja2;
        dxB = jb0; dyB = jb1; dzB = jb2;
    } else {
        const int P = (PS < 0) ? 0 : PS;
        dxA = ja0 - jxA[P]; dyA = ja1 - jyA[P]; dzA = ja2 - jzA[P];
        dxB = jb0 - jxB[P]; dyB = jb1 - jyB[P]; dzB = jb2 - jzB[P];
    }
    float boneA = fsqrt_ap(dxA*dxA + dyA*dyA + dzA*dzA);
    float boneB = fsqrt_ap(dxB*dxB + dyB*dyB + dzB*dzB);
    jxA[WS] = ja0; jyA[WS] = ja1; jzA[WS] = ja2;
    jxB[WS] = jb0; jyB[WS] = jb1; jzB[WS] = jb2;

    u64t xpA[10], xpB[10];
    xpA[0] = pk2(a0, a1); xpA[1] = pk2(a2, a3); xpA[2] = pk2(a4, a5);
    xpA[3] = pk2(a6, a7); xpA[4] = pk2(a8, ja0); xpA[5] = pk2(ja1, ja2);
    xpB[0] = pk2(b0, b1); xpB[1] = pk2(b2, b3); xpB[2] = pk2(b4, b5);
    xpB[3] = pk2(b6, b7); xpB[4] = pk2(b8, jb0); xpB[5] = pk2(jb1, jb2);
    if (PS < 0) {
        xpA[6] = gA[0]; xpA[7] = gA[1]; xpA[8] = gA[2];
        xpB[6] = gB[0]; xpB[7] = gB[1]; xpB[8] = gB[2];
    } else {
        const int P = (PS < 0) ? 0 : PS;
        xpA[6] = fA[P][0]; xpA[7] = fA[P][1]; xpA[8] = fA[P][2];
        xpB[6] = fB[P][0]; xpB[7] = fB[P][1]; xpB[8] = fB[P][2];
    }
    xpA[9] = pk2(boneA, boneA);        // hi weight is 0
    xpB[9] = pk2(boneB, boneB);

    // ---- layer 1: 10 rows (this half); weights loaded ONCE, feed both elements ----
    u64t accA[10], accB[10];
    {
        const ulonglong2* bb = (const ulonglong2*)(sm + OB1 + J*20 + 10*half);
        ulonglong2 c0 = bb[0], c1 = bb[1], c2 = bb[2], c3 = bb[3], c4 = bb[4];
        accA[0]=c0.x; accA[1]=c0.y; accA[2]=c1.x; accA[3]=c1.y; accA[4]=c2.x;
        accA[5]=c2.y; accA[6]=c3.x; accA[7]=c3.y; accA[8]=c4.x; accA[9]=c4.y;
#pragma unroll
        for (int r = 0; r < 10; ++r) accB[r] = accA[r];
    }
    const u64t* wb = sm + OW1 + (J*10)*20 + 10*half;
#pragma unroll
    for (int i = 0; i < 10; ++i) {
        const ulonglong2* wr = (const ulonglong2*)(wb + i*20);
        ulonglong2 wa = wr[0], wc = wr[1], wd = wr[2], we = wr[3], wf = wr[4];
        u64t xA = xpA[i], xB = xpB[i];
        accA[0] = fma2(xA, wa.x, accA[0]);  accB[0] = fma2(xB, wa.x, accB[0]);
        accA[1] = fma2(xA, wa.y, accA[1]);  accB[1] = fma2(xB, wa.y, accB[1]);
        accA[2] = fma2(xA, wc.x, accA[2]);  accB[2] = fma2(xB, wc.x, accB[2]);
        accA[3] = fma2(xA, wc.y, accA[3]);  accB[3] = fma2(xB, wc.y, accB[3]);
        accA[4] = fma2(xA, wd.x, accA[4]);  accB[4] = fma2(xB, wd.x, accB[4]);
        accA[5] = fma2(xA, wd.y, accA[5]);  accB[5] = fma2(xB, wd.y, accB[5]);
        accA[6] = fma2(xA, we.x, accA[6]);  accB[6] = fma2(xB, we.x, accB[6]);
        accA[7] = fma2(xA, we.y, accA[7]);  accB[7] = fma2(xB, we.y, accB[7]);
        accA[8] = fma2(xA, wf.x, accA[8]);  accB[8] = fma2(xB, wf.x, accB[8]);
        accA[9] = fma2(xA, wf.y, accA[9]);  accB[9] = fma2(xB, wf.y, accB[9]);
    }

    // combine even/odd-kp partials + relu
    float hsA[10], hsB[10];
#pragma unroll
    for (int r = 0; r < 10; ++r) {
        float a, b;
        unpk(accA[r], a, b); hsA[r] = fmaxf(a + b, 0.f);
        unpk(accB[r], a, b); hsB[r] = fmaxf(a + b, 0.f);
    }
    if (half) { hsA[9] = 1.0f; hsB[9] = 1.0f; }   // row 19 -> b2 row (k=19)

    // ---- layer 2: 15 shared LDS.128, dual FMA bursts ----
    ulonglong2 wz[15];
    {
        const ulonglong2* wp = (const ulonglong2*)(sm + OW2 + (J*20 + 10*half)*3);
#pragma unroll
        for (int i = 0; i < 15; ++i) wz[i] = wp[i];
    }
    u64t oA0 = 0ull, oA1 = 0ull, oA2 = 0ull;
    u64t oB0 = 0ull, oB1 = 0ull, oB2 = 0ull;
#pragma unroll
    for (int i = 0; i < 5; ++i) {
        u64t xA0 = pk2(hsA[2*i],   hsA[2*i]);
        u64t xA1 = pk2(hsA[2*i+1], hsA[2*i+1]);
        u64t xB0 = pk2(hsB[2*i],   hsB[2*i]);
        u64t xB1 = pk2(hsB[2*i+1], hsB[2*i+1]);
        oA0 = fma2(xA0, wz[3*i  ].x, oA0);  oB0 = fma2(xB0, wz[3*i  ].x, oB0);
        oA1 = fma2(xA0, wz[3*i  ].y, oA1);  oB1 = fma2(xB0, wz[3*i  ].y, oB1);
        oA2 = fma2(xA0, wz[3*i+1].x, oA2);  oB2 = fma2(xB0, wz[3*i+1].x, oB2);
        oA0 = fma2(xA1, wz[3*i+1].y, oA0);  oB0 = fma2(xB1, wz[3*i+1].y, oB0);
        oA1 = fma2(xA1, wz[3*i+2].x, oA1);  oB1 = fma2(xB1, wz[3*i+2].x, oB1);
        oA2 = fma2(xA1, wz[3*i+2].y, oA2);  oB2 = fma2(xB1, wz[3*i+2].y, oB2);
    }
    oA0 = add2(oA0, shx1(oA0));
    oA1 = add2(oA1, shx1(oA1));
    oA2 = add2(oA2, shx1(oA2));
    oB0 = add2(oB0, shx1(oB0));
    oB1 = add2(oB1, shx1(oB1));
    oB2 = add2(oB2, shx1(oB2));

    fA[WS][0] = oA0; fA[WS][1] = oA1; fA[WS][2] = oA2;
    fB[WS][0] = oB0; fB[WS][1] = oB1; fB[WS][2] = oB2;

    // direct global stores: even lane writes element A's 6 floats, odd writes B's
    if (half == 0) {
        u64t* d = (u64t*)(oeA + 6*J);
        d[0] = oA0; d[1] = oA1; d[2] = oA2;
    } else {
        u64t* d = (u64t*)(oeB + 6*J);
        d[0] = oB0; d[1] = oB1; d[2] = oB2;
    }
}

__global__ void __launch_bounds__(256, 1)
pose_kernel(const float* __restrict__ rots, const float* __restrict__ jtrs,
            const float* __restrict__ W0, const float* __restrict__ b0,
            const float* __restrict__ W1, const float* __restrict__ b1,
            const float* __restrict__ W2, const float* __restrict__ b2,
            float* __restrict__ out)
{
    extern __shared__ u64t sm[];
    const int tid = threadIdx.x;

    // ---- weight packing (R10 layout; sW0 unpermuted) ----
    for (int idx = tid; idx < 24*10*20; idx += 256) {   // sW1' [j][kp][20 r]
        int r = idx % 20; int t = idx / 20; int i = t % 10; int j = t / 10;
        int m0 = 2*i, m1 = 2*i + 1;
        float lo = 0.f, hi = 0.f;
        if (r < 19) {
            int k0 = (m0 < 12) ? m0 : (m0 < 18 ? m0 + 1 : 12);
            lo = W1[(j*19 + r)*19 + k0];
            if (m1 < 19) {
                int k1 = (m1 < 12) ? m1 : (m1 < 18 ? m1 + 1 : 12);
                hi = W1[(j*19 + r)*19 + k1];
            }
        }
        sm[OW1 + idx] = pk2(lo, hi);
    }
    for (int idx = tid; idx < 24*20*3; idx += 256) {    // sW2 [j][20 k][3 dp]
        int dp = idx % 3; int t = idx / 3; int k = t % 20; int j = t / 20;
        float lo, hi;
        if (k < 19) { lo = W2[(j*6 + 2*dp)*19 + k]; hi = W2[(j*6 + 2*dp + 1)*19 + k]; }
        else        { lo = b2[j*6 + 2*dp];          hi = b2[j*6 + 2*dp + 1]; }
        sm[OW2 + idx] = pk2(lo, hi);
    }
    for (int idx = tid; idx < 144*6; idx += 256) {      // sW0' [144 kp][6 d]
        int d = idx % 6; int kp = idx / 6;
        sm[OW0 + idx] = pk2(W0[d*288 + 2*kp], W0[d*288 + 2*kp + 1]);
    }
    for (int idx = tid; idx < 24*20; idx += 256) {      // sB1' [j][20 r]
        int r = idx % 20; int j = idx / 20;
        float lo = (r < 19) ? b1[j*19 + r] : 0.f;
        sm[OB1 + idx] = pk2(lo, 0.f);
    }
    if (tid < 6) sm[OB0 + tid] = pk2(b0[tid], 0.f);
    __syncthreads();

    const int p    = tid >> 1;          // lane pair index
    const int half = tid & 1;           // row/k half
    size_t eA = (size_t)blockIdx.x * 256 + 2*p;
    size_t eB = eA + 1;

    const float* reA = rots + eA * 216;
    const float* teA = jtrs + eA * 72;
    float*       oeA = out  + eA * 144;
    const float* reB = rots + eB * 216;
    const float* teB = jtrs + eB * 72;
    float*       oeB = out  + eB * 144;

    // ---- pass 1: gfeat partials for both elements, shared weight loads ----
    u64t a6A[6], a6B[6];
    if (half == 0) {
#pragma unroll
        for (int d = 0; d < 6; ++d) { a6A[d] = sm[OB0 + d]; a6B[d] = a6A[d]; }
    } else {
#pragma unroll
        for (int d = 0; d < 6; ++d) { a6A[d] = 0ull; a6B[d] = 0ull; }
    }
    {
        // half 0: features   0..143 -> re[0..144)
        // half 1: features 144..287 -> re[144..216) ++ te[0..72)
        const float4* sA0 = (half == 0) ? (const float4*)reA        : (const float4*)(reA + 144);
        const float4* sA1 = (half == 0) ? (const float4*)(reA + 72) : (const float4*)teA;
        const float4* sB0 = (half == 0) ? (const float4*)reB        : (const float4*)(reB + 144);
        const float4* sB1 = (half == 0) ? (const float4*)(reB + 72) : (const float4*)teB;
        const u64t* wbase = sm + OW0 + (72*half)*6;
#pragma unroll 4
        for (int q = 0; q < 36; ++q) {
            float4 xa = (q < 18) ? sA0[q] : sA1[q - 18];
            float4 xb = (q < 18) ? sB0[q] : sB1[q - 18];
            u64t xaLo = pk2(xa.x, xa.y), xaHi = pk2(xa.z, xa.w);
            u64t xbLo = pk2(xb.x, xb.y), xbHi = pk2(xb.z, xb.w);
            const ulonglong2* wp = (const ulonglong2*)(wbase + q*12);
            ulonglong2 w0 = wp[0], w1 = wp[1], w2 = wp[2];
            ulonglong2 w3 = wp[3], w4 = wp[4], w5 = wp[5];
            a6A[0] = fma2(xaLo, w0.x, a6A[0]);  a6B[0] = fma2(xbLo, w0.x, a6B[0]);
            a6A[1] = fma2(xaLo, w0.y, a6A[1]);  a6B[1] = fma2(xbLo, w0.y, a6B[1]);
            a6A[2] = fma2(xaLo, w1.x, a6A[2]);  a6B[2] = fma2(xbLo, w1.x, a6B[2]);
            a6A[3] = fma2(xaLo, w1.y, a6A[3]);  a6B[3] = fma2(xbLo, w1.y, a6B[3]);
            a6A[4] = fma2(xaLo, w2.x, a6A[4]);  a6B[4] = fma2(xbLo, w2.x, a6B[4]);
            a6A[5] = fma2(xaLo, w2.y, a6A[5]);  a6B[5] = fma2(xbLo, w2.y, a6B[5]);
            a6A[0] = fma2(xaHi, w3.x, a6A[0]);  a6B[0] = fma2(xbHi, w3.x, a6B[0]);
            a6A[1] = fma2(xaHi, w3.y, a6A[1]);  a6B[1] = fma2(xbHi, w3.y, a6B[1]);
            a6A[2] = fma2(xaHi, w4.x, a6A[2]);  a6B[2] = fma2(xbHi, w4.x, a6B[2]);
            a6A[3] = fma2(xaHi, w4.y, a6A[3]);  a6B[3] = fma2(xbHi, w4.y, a6B[3]);
            a6A[4] = fma2(xaHi, w5.x, a6A[4]);  a6B[4] = fma2(xbHi, w5.x, a6B[4]);
            a6A[5] = fma2(xaHi, w5.y, a6A[5]);  a6B[5] = fma2(xbHi, w5.y, a6B[5]);
        }
    }
    u64t gA[3], gB[3];
#pragma unroll
    for (int dp = 0; dp < 3; ++dp) {
        float a0, a1, c0, c1;
        unpk(a6A[2*dp],     a0, a1);
        unpk(a6A[2*dp + 1], c0, c1);
        u64t pr = pk2(a0 + a1, c0 + c1);
        gA[dp] = add2(pr, shx1(pr));
        unpk(a6B[2*dp],     a0, a1);
        unpk(a6B[2*dp + 1], c0, c1);
        pr = pk2(a0 + a1, c0 + c1);
        gB[dp] = add2(pr, shx1(pr));
    }

    // ---- pass 2: joint chain, 4-slot register liveness, dual elements ----
    u64t fA[4][3], fB[4][3];
    float jxA[4], jyA[4], jzA[4], jxB[4], jyB[4], jzB[4];

    do_joint< 0,-1,0>(reA, teA, reB, teB, oeA, oeB, half, sm, fA, fB, jxA, jyA, jzA, jxB, jyB, jzB, gA, gB);
    do_joint< 1, 0,1>(reA, teA, reB, teB, oeA, oeB, half, sm, fA, fB, jxA, jyA, jzA, jxB, jyB, jzB, gA, gB);
    do_joint< 2, 0,2>(reA, teA, reB, teB, oeA, oeB, half, sm, fA, fB, jxA, jyA, jzA, jxB, jyB, jzB, gA, gB);
    do_joint< 3, 0,3>(reA, teA, reB, teB, oeA, oeB, half, sm, fA, fB, jxA, jyA, jzA, jxB, jyB, jzB, gA, gB);
    do_joint< 4, 1,0>(reA, teA, reB, teB, oeA, oeB, half, sm, fA, fB, jxA, jyA, jzA, jxB, jyB, jzB, gA, gB);
    do_joint< 5, 2,1>(reA, teA, reB, teB, oeA, oeB, half, sm, fA, fB, jxA, jyA, jzA, jxB, jyB, jzB, gA, gB);
    do_joint< 6, 3,2>(reA, teA, reB, teB, oeA, oeB, half, sm, fA, fB, jxA, jyA, jzA, jxB, jyB, jzB, gA, gB);
    do_joint< 7, 0,3>(reA, teA, reB, teB, oeA, oeB, half, sm, fA, fB, jxA, jyA, jzA, jxB, jyB, jzB, gA, gB);
    do_joint< 8, 1,0>(reA, teA, reB, teB, oeA, oeB, half, sm, fA, fB, jxA, jyA, jzA, jxB, jyB, jzB, gA, gB);
    do_joint< 9, 2,1>(reA, teA, reB, teB, oeA, oeB, half, sm, fA, fB, jxA, jyA, jzA, jxB, jyB, jzB, gA, gB);
    do_joint<10, 3,2>(reA, teA, reB, teB, oeA, oeB, half, sm, fA, fB, jxA, jyA, jzA, jxB, jyB, jzB, gA, gB);
    do_joint<11, 0,2>(reA, teA, reB, teB, oeA, oeB, half, sm, fA, fB, jxA, jyA, jzA, jxB, jyB, jzB, gA, gB);
    do_joint<12, 1,2>(reA, teA, reB, teB, oeA, oeB, half, sm, fA, fB, jxA, jyA, jzA, jxB, jyB, jzB, gA, gB);
    do_joint<13, 1,0>(reA, teA, reB, teB, oeA, oeB, half, sm, fA, fB, jxA, jyA, jzA, jxB, jyB, jzB, gA, gB);
    do_joint<14, 1,3>(reA, teA, reB, teB, oeA, oeB, half, sm, fA, fB, jxA, jyA, jzA, jxB, jyB, jzB, gA, gB);
    do_joint<15, 2,1>(reA, teA, reB, teB, oeA, oeB, half, sm, fA, fB, jxA, jyA, jzA, jxB, jyB, jzB, gA, gB);
    do_joint<16, 0,1>(reA, teA, reB, teB, oeA, oeB, half, sm, fA, fB, jxA, jyA, jzA, jxB, jyB, jzB, gA, gB);
    do_joint<17, 3,0>(reA, teA, reB, teB, oeA, oeB, half, sm, fA, fB, jxA, jyA, jzA, jxB, jyB, jzB, gA, gB);
    do_joint<18, 1,3>(reA, teA, reB, teB, oeA, oeB, half, sm, fA, fB, jxA, jyA, jzA, jxB, jyB, jzB, gA, gB);
    do_joint<19, 0,1>(reA, teA, reB, teB, oeA, oeB, half, sm, fA, fB, jxA, jyA, jzA, jxB, jyB, jzB, gA, gB);
    do_joint<20, 3,0>(reA, teA, reB, teB, oeA, oeB, half, sm, fA, fB, jxA, jyA, jzA, jxB, jyB, jzB, gA, gB);
    do_joint<21, 1,3>(reA, teA, reB, teB, oeA, oeB, half, sm, fA, fB, jxA, jyA, jzA, jxB, jyB, jzB, gA, gB);
    do_joint<22, 0,1>(reA, teA, reB, teB, oeA, oeB, half, sm, fA, fB, jxA, jyA, jzA, jxB, jyB, jzB, gA, gB);
    do_joint<23, 3,0>(reA, teA, reB, teB, oeA, oeB, half, sm, fA, fB, jxA, jyA, jzA, jxB, jyB, jzB, gA, gB);
}

extern "C" void kernel_launch(void* const* d_in, const int* in_sizes, int n_in,
                              void* d_out, int out_size) {
    (void)n_in; (void)out_size;
    const float* rots = (const float*)d_in[0];
    const float* jtrs = (const float*)d_in[1];
    const float* W0   = (const float*)d_in[2];
    const float* b0   = (const float*)d_in[3];
    const float* W1   = (const float*)d_in[4];
    const float* b1   = (const float*)d_in[5];
    const float* W2   = (const float*)d_in[6];
    const float* b2   = (const float*)d_in[7];
    float* out = (float*)d_out;

    int n = in_sizes[0] / 216;        // B (131072 -> divisible by 256)
    int grid = n / 256;

    cudaFuncSetAttribute(pose_kernel, cudaFuncAttributeMaxDynamicSharedMemorySize, SMEM_BYTES);
    pose_kernel<<<grid, 256, SMEM_BYTES>>>(rots, jtrs, W0, b0, W1, b1, W2, b2, out);
}